// round 1
// baseline (speedup 1.0000x reference)
#include <cuda_runtime.h>
#include <cstdint>

// ---------------- scratch (no allocations allowed -> __device__ globals) ----
// qkv:    (16384, 3072)
// qproj:  (b,h,n,f) = (4,16,4096,256)
// kproj:  same
// kv:     (b,h, 256, 64)
// ksum:   (b,h, 256)
// attn:   (16384, 1024)
__device__ float g_qkv[50331648];
__device__ float g_qproj[67108864];
__device__ float g_kproj[67108864];
__device__ float g_kv[1048576];
__device__ float g_ksum[16384];
__device__ float g_attn[16777216];

// ---------------- generic SGEMM: C = A(MxK) @ B(KxN) [+ bias] --------------
// BM=128, BN=128, BK=8, 256 threads, 8x8 per-thread microtile.
// Requires M%128==0, N%128==0, K%8==0.
template<bool BIAS>
__global__ __launch_bounds__(256) void sgemm_kernel(
    const float* __restrict__ A, const float* __restrict__ B,
    const float* __restrict__ bias, float* __restrict__ C,
    int M, int N, int K)
{
    __shared__ float Ast[8][132];   // transposed A tile, padded (132%4==0 keeps f4 align)
    __shared__ float Bs[8][128];

    const int tid = threadIdx.x;
    const int tx = tid & 15, ty = tid >> 4;
    const int rowbase = blockIdx.y * 128;
    const int colbase = blockIdx.x * 128;

    const float* Ag = A + (size_t)rowbase * K;
    const float* Bg = B + colbase;

    const int arow = tid >> 1,  ac4 = (tid & 1) * 4;
    const int brow = tid >> 5,  bc4 = (tid & 31) * 4;

    float acc[8][8];
    #pragma unroll
    for (int i = 0; i < 8; i++)
        #pragma unroll
        for (int j = 0; j < 8; j++) acc[i][j] = 0.f;

    for (int k0 = 0; k0 < K; k0 += 8) {
        float4 av = *(const float4*)(Ag + (size_t)arow * K + k0 + ac4);
        Ast[ac4 + 0][arow] = av.x;
        Ast[ac4 + 1][arow] = av.y;
        Ast[ac4 + 2][arow] = av.z;
        Ast[ac4 + 3][arow] = av.w;
        *(float4*)(&Bs[brow][bc4]) =
            *(const float4*)(Bg + (size_t)(k0 + brow) * N + bc4);
        __syncthreads();

        #pragma unroll
        for (int k = 0; k < 8; k++) {
            float4 a0 = *(const float4*)(&Ast[k][ty * 8]);
            float4 a1 = *(const float4*)(&Ast[k][ty * 8 + 4]);
            float4 b0 = *(const float4*)(&Bs[k][tx * 8]);
            float4 b1 = *(const float4*)(&Bs[k][tx * 8 + 4]);
            float ra[8] = {a0.x, a0.y, a0.z, a0.w, a1.x, a1.y, a1.z, a1.w};
            float rb[8] = {b0.x, b0.y, b0.z, b0.w, b1.x, b1.y, b1.z, b1.w};
            #pragma unroll
            for (int i = 0; i < 8; i++)
                #pragma unroll
                for (int j = 0; j < 8; j++)
                    acc[i][j] += ra[i] * rb[j];
        }
        __syncthreads();
    }

    #pragma unroll
    for (int i = 0; i < 8; i++) {
        int r = rowbase + ty * 8 + i;
        float* Cp = C + (size_t)r * N + colbase + tx * 8;
        float4 o0, o1;
        o0.x = acc[i][0]; o0.y = acc[i][1]; o0.z = acc[i][2]; o0.w = acc[i][3];
        o1.x = acc[i][4]; o1.y = acc[i][5]; o1.z = acc[i][6]; o1.w = acc[i][7];
        if (BIAS) {
            const float* bp = bias + colbase + tx * 8;
            o0.x += bp[0]; o0.y += bp[1]; o0.z += bp[2]; o0.w += bp[3];
            o1.x += bp[4]; o1.y += bp[5]; o1.z += bp[6]; o1.w += bp[7];
        }
        *(float4*)(Cp)     = o0;
        *(float4*)(Cp + 4) = o1;
    }
}

// ---------------- per-head feature projection + elu1 -----------------------
// For head h, sel in {q=0,k=1}:
//   out[(b,h,n,f)] = elu1( qkv[b,n, sel*1024 + h*64 + :64] @ proj[h] )
// grid: (f-tile 0..1, row-tile 0..127, z = h*2+sel : 0..31), 256 threads
__global__ __launch_bounds__(256) void proj_kernel(const float* __restrict__ proj)
{
    const int z = blockIdx.z;
    const int sel = z & 1;
    const int h = z >> 1;

    __shared__ float Ast[32][132];
    __shared__ float Bs[32][128];

    const int tid = threadIdx.x;
    const int tx = tid & 15, ty = tid >> 4;
    const int rowbase = blockIdx.y * 128;
    const int fbase = blockIdx.x * 128;

    const int aoff = sel * 1024 + h * 64;
    const float* Bg = proj + h * 64 * 256 + fbase;

    float acc[8][8];
    #pragma unroll
    for (int i = 0; i < 8; i++)
        #pragma unroll
        for (int j = 0; j < 8; j++) acc[i][j] = 0.f;

    for (int k0 = 0; k0 < 64; k0 += 32) {
        #pragma unroll
        for (int i = 0; i < 4; i++) {
            int idx = tid + i * 256;
            // A tile: 128 rows x 32 k
            int row = idx >> 3, c4 = (idx & 7) * 4;
            float4 av = *(const float4*)(
                &g_qkv[(size_t)(rowbase + row) * 3072 + aoff + k0 + c4]);
            Ast[c4 + 0][row] = av.x;
            Ast[c4 + 1][row] = av.y;
            Ast[c4 + 2][row] = av.z;
            Ast[c4 + 3][row] = av.w;
            // B tile: 32 k x 128 f
            int brow = idx >> 5, bc4 = (idx & 31) * 4;
            *(float4*)(&Bs[brow][bc4]) =
                *(const float4*)(Bg + (k0 + brow) * 256 + bc4);
        }
        __syncthreads();

        #pragma unroll
        for (int k = 0; k < 32; k++) {
            float4 a0 = *(const float4*)(&Ast[k][ty * 8]);
            float4 a1 = *(const float4*)(&Ast[k][ty * 8 + 4]);
            float4 b0 = *(const float4*)(&Bs[k][tx * 8]);
            float4 b1 = *(const float4*)(&Bs[k][tx * 8 + 4]);
            float ra[8] = {a0.x, a0.y, a0.z, a0.w, a1.x, a1.y, a1.z, a1.w};
            float rb[8] = {b0.x, b0.y, b0.z, b0.w, b1.x, b1.y, b1.z, b1.w};
            #pragma unroll
            for (int i = 0; i < 8; i++)
                #pragma unroll
                for (int j = 0; j < 8; j++)
                    acc[i][j] += ra[i] * rb[j];
        }
        __syncthreads();
    }

    float* out = sel ? g_kproj : g_qproj;
    #pragma unroll
    for (int i = 0; i < 8; i++) {
        int r = rowbase + ty * 8 + i;          // global row in [0,16384)
        int b = r >> 12, n = r & 4095;
        size_t crow = (((size_t)(b * 16 + h) * 4096 + n) * 256) + fbase + tx * 8;
        float4 o0, o1;
        float v;
        v = acc[i][0]; o0.x = v > 0.f ? v + 1.f : __expf(v);
        v = acc[i][1]; o0.y = v > 0.f ? v + 1.f : __expf(v);
        v = acc[i][2]; o0.z = v > 0.f ? v + 1.f : __expf(v);
        v = acc[i][3]; o0.w = v > 0.f ? v + 1.f : __expf(v);
        v = acc[i][4]; o1.x = v > 0.f ? v + 1.f : __expf(v);
        v = acc[i][5]; o1.y = v > 0.f ? v + 1.f : __expf(v);
        v = acc[i][6]; o1.z = v > 0.f ? v + 1.f : __expf(v);
        v = acc[i][7]; o1.w = v > 0.f ? v + 1.f : __expf(v);
        *(float4*)(&out[crow])     = o0;
        *(float4*)(&out[crow + 4]) = o1;
    }
}

// ---------------- kv state: kv[b,h,f,d] = sum_n kproj[b,h,n,f] * v[b,n,h,d] -
// also k_sum[b,h,f] = sum_n kproj[b,h,n,f]
// grid: (f-tile 0..3 [64 f each], bh 0..63), 256 threads (16x16), 4x4 microtile
__global__ __launch_bounds__(256) void kv_kernel()
{
    const int bh = blockIdx.y;
    const int b = bh >> 4, h = bh & 15;
    const int fbase = blockIdx.x * 64;

    __shared__ float As[32][64];   // [n][f]
    __shared__ float Bs[32][64];   // [n][d]

    const int tid = threadIdx.x;
    const int tf = tid >> 4, td = tid & 15;

    float acc[4][4];
    #pragma unroll
    for (int i = 0; i < 4; i++)
        #pragma unroll
        for (int j = 0; j < 4; j++) acc[i][j] = 0.f;
    float ks[4] = {0.f, 0.f, 0.f, 0.f};

    const float* kp = g_kproj + (size_t)bh * 4096 * 256;
    const size_t voff = 2048 + h * 64;

    for (int n0 = 0; n0 < 4096; n0 += 32) {
        #pragma unroll
        for (int i = 0; i < 2; i++) {
            int idx = tid + i * 256;
            int row = idx >> 4, c4 = (idx & 15) * 4;
            *(float4*)(&As[row][c4]) =
                *(const float4*)(kp + (size_t)(n0 + row) * 256 + fbase + c4);
            *(float4*)(&Bs[row][c4]) =
                *(const float4*)(&g_qkv[(size_t)(b * 4096 + n0 + row) * 3072 + voff + c4]);
        }
        __syncthreads();

        #pragma unroll
        for (int n = 0; n < 32; n++) {
            float4 a  = *(const float4*)(&As[n][tf * 4]);
            float4 bv = *(const float4*)(&Bs[n][td * 4]);
            float ra[4] = {a.x, a.y, a.z, a.w};
            float rb[4] = {bv.x, bv.y, bv.z, bv.w};
            #pragma unroll
            for (int i = 0; i < 4; i++) {
                #pragma unroll
                for (int j = 0; j < 4; j++)
                    acc[i][j] += ra[i] * rb[j];
                ks[i] += ra[i];   // redundant across td; only td==0 stores
            }
        }
        __syncthreads();
    }

    #pragma unroll
    for (int i = 0; i < 4; i++) {
        size_t row = (size_t)bh * 256 + fbase + tf * 4 + i;
        float4 o;
        o.x = acc[i][0]; o.y = acc[i][1]; o.z = acc[i][2]; o.w = acc[i][3];
        *(float4*)(&g_kv[row * 64 + td * 4]) = o;
        if (td == 0) g_ksum[row] = ks[i];
    }
}

// ---------------- attn: out[b,n,h*64+d] = (qproj @ kv) / (qproj . ksum + eps)
// grid: (n-tile 0..31 [128 rows], bh 0..63), 256 threads (16x16), 8x4 microtile
__global__ __launch_bounds__(256) void attn_kernel()
{
    const int bh = blockIdx.y;
    const int b = bh >> 4, h = bh & 15;
    const int nbase = blockIdx.x * 128;

    __shared__ float Ast[16][132];  // [k][n] transposed qproj tile
    __shared__ float Bs[16][64];    // [k][d] kv tile
    __shared__ float kss[16];

    const int tid = threadIdx.x;
    const int tr = tid >> 4, tc = tid & 15;

    float acc[8][4];
    #pragma unroll
    for (int i = 0; i < 8; i++)
        #pragma unroll
        for (int j = 0; j < 4; j++) acc[i][j] = 0.f;
    float zacc[8] = {0.f, 0.f, 0.f, 0.f, 0.f, 0.f, 0.f, 0.f};

    const float* qp = g_qproj + (size_t)bh * 4096 * 256 + (size_t)nbase * 256;
    const float* kvp = g_kv + (size_t)bh * 256 * 64;
    const float* ksp = g_ksum + (size_t)bh * 256;

    for (int k0 = 0; k0 < 256; k0 += 16) {
        #pragma unroll
        for (int i = 0; i < 2; i++) {
            int idx = tid + i * 256;
            int row = idx >> 2, c4 = (idx & 3) * 4;
            float4 av = *(const float4*)(qp + (size_t)row * 256 + k0 + c4);
            Ast[c4 + 0][row] = av.x;
            Ast[c4 + 1][row] = av.y;
            Ast[c4 + 2][row] = av.z;
            Ast[c4 + 3][row] = av.w;
        }
        {
            int row = tid >> 4, c4 = (tid & 15) * 4;
            *(float4*)(&Bs[row][c4]) = *(const float4*)(kvp + (k0 + row) * 64 + c4);
        }
        if (tid < 16) kss[tid] = ksp[k0 + tid];
        __syncthreads();

        #pragma unroll
        for (int k = 0; k < 16; k++) {
            float4 a0 = *(const float4*)(&Ast[k][tr * 8]);
            float4 a1 = *(const float4*)(&Ast[k][tr * 8 + 4]);
            float4 bv = *(const float4*)(&Bs[k][tc * 4]);
            float ra[8] = {a0.x, a0.y, a0.z, a0.w, a1.x, a1.y, a1.z, a1.w};
            float rb[4] = {bv.x, bv.y, bv.z, bv.w};
            float kk = kss[k];
            #pragma unroll
            for (int i = 0; i < 8; i++) {
                #pragma unroll
                for (int j = 0; j < 4; j++)
                    acc[i][j] += ra[i] * rb[j];
                zacc[i] += ra[i] * kk;
            }
        }
        __syncthreads();
    }

    #pragma unroll
    for (int i = 0; i < 8; i++) {
        int r = tr * 8 + i;
        float zi = 1.0f / (zacc[i] + 1e-8f);
        float4 o;
        o.x = acc[i][0] * zi; o.y = acc[i][1] * zi;
        o.z = acc[i][2] * zi; o.w = acc[i][3] * zi;
        *(float4*)(&g_attn[(size_t)(b * 4096 + nbase + r) * 1024 + h * 64 + tc * 4]) = o;
    }
}

// ---------------------------------------------------------------------------
extern "C" void kernel_launch(void* const* d_in, const int* in_sizes, int n_in,
                              void* d_out, int out_size)
{
    const float* x      = (const float*)d_in[0];  // (4,4096,1024)
    const float* w_qkv  = (const float*)d_in[1];  // (1024,3072)
    const float* proj   = (const float*)d_in[2];  // (16,64,256)
    const float* w_out  = (const float*)d_in[3];  // (1024,1024)
    const float* b_out  = (const float*)d_in[4];  // (1024,)
    float* out = (float*)d_out;                   // (4,4096,1024)

    float *qkv_p, *attn_p;
    cudaGetSymbolAddress((void**)&qkv_p, g_qkv);
    cudaGetSymbolAddress((void**)&attn_p, g_attn);

    // 1) qkv = x @ w_qkv            (16384 x 3072, K=1024)
    sgemm_kernel<false><<<dim3(24, 128), 256>>>(x, w_qkv, nullptr, qkv_p,
                                                16384, 3072, 1024);
    // 2) q_proj / k_proj = elu1(head-slice @ proj[h])
    proj_kernel<<<dim3(2, 128, 32), 256>>>(proj);
    // 3) kv state + k_sum
    kv_kernel<<<dim3(4, 64), 256>>>();
    // 4) attn + z normalization -> g_attn (b,n,1024)
    attn_kernel<<<dim3(32, 64), 256>>>();
    // 5) out = attn @ w_out + b_out (16384 x 1024, K=1024)
    sgemm_kernel<true><<<dim3(8, 128), 256>>>(attn_p, w_out, b_out, out,
                                              16384, 1024, 1024);
}

// round 3
// speedup vs baseline: 1.7104x; 1.7104x over previous
#include <cuda_runtime.h>
#include <cuda_bf16.h>
#include <cstdint>

// ======================= device scratch (no allocs) =========================
__device__ float g_qkv[50331648];                 // (16384, 3072)
__device__ float g_qproj[67108864];               // (4,16,4096,256)
__device__ float g_kproj[67108864];
__device__ float g_kv[1048576];                   // (4,16,256,64)
__device__ float g_ksum[16384];                   // (4,16,256)
__device__ __nv_bfloat16 g_xhi[16777216];         // x split (16384,1024)
__device__ __nv_bfloat16 g_xlo[16777216];
__device__ __nv_bfloat16 g_wqkvT_hi[3145728];     // w_qkv^T (3072,1024)
__device__ __nv_bfloat16 g_wqkvT_lo[3145728];
__device__ __nv_bfloat16 g_woutT_hi[1048576];     // w_out^T (1024,1024)
__device__ __nv_bfloat16 g_woutT_lo[1048576];
__device__ __nv_bfloat16 g_attn_hi[16777216];     // attn (16384,1024) split
__device__ __nv_bfloat16 g_attn_lo[16777216];

// ======================= PTX helpers (baseline ISA only) ====================
__device__ __forceinline__ uint32_t smem_u32(const void* p) {
    uint32_t a;
    asm("{ .reg .u64 t; cvta.to.shared.u64 t, %1; cvt.u32.u64 %0, t; }"
        : "=r"(a) : "l"(p));
    return a;
}
__device__ __forceinline__ void cp16(uint32_t saddr, const void* g) {
    asm volatile("cp.async.cg.shared.global [%0], [%1], 16;"
                 :: "r"(saddr), "l"(g) : "memory");
}
#define CP_COMMIT() asm volatile("cp.async.commit_group;" ::: "memory")
#define CP_WAIT1()  asm volatile("cp.async.wait_group 1;" ::: "memory")
#define CP_WAIT0()  asm volatile("cp.async.wait_group 0;" ::: "memory")

__device__ __forceinline__ void ldsm4(uint32_t& r0, uint32_t& r1,
                                      uint32_t& r2, uint32_t& r3, uint32_t a) {
    asm volatile("ldmatrix.sync.aligned.m8n8.x4.shared.b16 {%0,%1,%2,%3}, [%4];"
                 : "=r"(r0), "=r"(r1), "=r"(r2), "=r"(r3) : "r"(a));
}
__device__ __forceinline__ void mma16816(float* c, const uint32_t* a,
                                         const uint32_t* b) {
    asm volatile(
        "mma.sync.aligned.m16n8k16.row.col.f32.bf16.bf16.f32 "
        "{%0,%1,%2,%3}, {%4,%5,%6,%7}, {%8,%9}, {%0,%1,%2,%3};"
        : "+f"(c[0]), "+f"(c[1]), "+f"(c[2]), "+f"(c[3])
        : "r"(a[0]), "r"(a[1]), "r"(a[2]), "r"(a[3]), "r"(b[0]), "r"(b[1]));
}

// ======================= HMMA GEMM ==========================================
// C(M,N) = (Ahi+Alo)(M,K) @ (Bhi+Blo)(N,K)^T [+ bias], fp32 out.
// 3-term split. 128x128x32 CTA tile, 8 warps (4 M x 2 N), 32x64 warp tile.
// Smem: pitch-144B rows (72 bf16) -> conflict-free ldmatrix without swizzle.
static constexpr int PITCH_B = 144;                 // bytes per 32-elem k row
static constexpr int TILE_B  = 128 * PITCH_B;       // 18432 per operand tile
static constexpr int STAGE_B = 4 * TILE_B;          // Ah, Al, Bh, Bl
static constexpr int GEMM_SMEM = 2 * STAGE_B;       // 147456

template<bool BIAS>
__global__ __launch_bounds__(256, 1) void hmma_gemm(
    const __nv_bfloat16* __restrict__ Ahi, const __nv_bfloat16* __restrict__ Alo,
    const __nv_bfloat16* __restrict__ Bhi, const __nv_bfloat16* __restrict__ Blo,
    const float* __restrict__ bias, float* __restrict__ C, int N, int K)
{
    extern __shared__ char smem[];
    const uint32_t sbase = smem_u32(smem);
    const int tid = threadIdx.x;
    const int wid = tid >> 5, lane = tid & 31;
    const int warpM = wid & 3, warpN = wid >> 2;
    const int m0 = blockIdx.y * 128;
    const int n0 = blockIdx.x * 128;

    const __nv_bfloat16* gsrc[4] = {Ahi, Alo, Bhi, Blo};
    const int gbase[4] = {m0, m0, n0, n0};

    float acc[2][8][4];
    #pragma unroll
    for (int i = 0; i < 2; i++)
        #pragma unroll
        for (int j = 0; j < 8; j++)
            #pragma unroll
            for (int q = 0; q < 4; q++) acc[i][j][q] = 0.f;

    const int NC = K >> 5;   // BK = 32

    // --- stage loader: 4 tiles x 128 rows x 4 chunks(16B) = 2048 cp.async ---
    auto load_stage = [&](int c, int s) {
        const uint32_t sb = sbase + s * STAGE_B;
        #pragma unroll
        for (int i = 0; i < 8; i++) {
            int idx = tid + i * 256;
            int t = idx >> 9;
            int rem = idx & 511;
            int row = rem >> 2, ch = rem & 3;
            const __nv_bfloat16* g =
                gsrc[t] + (size_t)(gbase[t] + row) * K + c * 32 + ch * 8;
            cp16(sb + t * TILE_B + row * PITCH_B + ch * 16, g);
        }
        CP_COMMIT();
    };

    load_stage(0, 0);

    for (int c = 0; c < NC; c++) {
        const int s = c & 1;
        if (c + 1 < NC) { load_stage(c + 1, s ^ 1); CP_WAIT1(); }
        else            { CP_WAIT0(); }
        __syncthreads();

        const uint32_t sb = sbase + s * STAGE_B;
        const uint32_t Ah = sb, Al = sb + TILE_B;
        const uint32_t Bh = sb + 2 * TILE_B, Bl = sb + 3 * TILE_B;

        #pragma unroll
        for (int ks = 0; ks < 2; ks++) {
            uint32_t ahi[2][4], alo[2][4], bhi[8][2], blo[8][2];
            // A fragments: rows warpM*32 + mt*16 + (lane&15), chunk ks*2+(lane>>4)
            #pragma unroll
            for (int mt = 0; mt < 2; mt++) {
                int r = warpM * 32 + mt * 16 + (lane & 15);
                uint32_t off = r * PITCH_B + (ks * 2 + (lane >> 4)) * 16;
                ldsm4(ahi[mt][0], ahi[mt][1], ahi[mt][2], ahi[mt][3], Ah + off);
                ldsm4(alo[mt][0], alo[mt][1], alo[mt][2], alo[mt][3], Al + off);
            }
            // B fragments: 8 n8-tiles per warp, 2 tiles per ldmatrix.x4
            #pragma unroll
            for (int tp = 0; tp < 4; tp++) {
                int nr = warpN * 64 + tp * 16 + ((lane >> 4) << 3) + (lane & 7);
                uint32_t off = nr * PITCH_B + (ks * 2 + ((lane >> 3) & 1)) * 16;
                ldsm4(bhi[2 * tp][0], bhi[2 * tp][1],
                      bhi[2 * tp + 1][0], bhi[2 * tp + 1][1], Bh + off);
                ldsm4(blo[2 * tp][0], blo[2 * tp][1],
                      blo[2 * tp + 1][0], blo[2 * tp + 1][1], Bl + off);
            }
            #pragma unroll
            for (int mt = 0; mt < 2; mt++)
                #pragma unroll
                for (int nt = 0; nt < 8; nt++) {
                    mma16816(acc[mt][nt], ahi[mt], bhi[nt]);
                    mma16816(acc[mt][nt], ahi[mt], blo[nt]);
                    mma16816(acc[mt][nt], alo[mt], bhi[nt]);
                }
        }
        __syncthreads();
    }

    // --- epilogue ---
    #pragma unroll
    for (int mt = 0; mt < 2; mt++) {
        int r0 = m0 + warpM * 32 + mt * 16 + (lane >> 2);
        #pragma unroll
        for (int nt = 0; nt < 8; nt++) {
            int col = n0 + warpN * 64 + nt * 8 + (lane & 3) * 2;
            float2 v0 = {acc[mt][nt][0], acc[mt][nt][1]};
            float2 v1 = {acc[mt][nt][2], acc[mt][nt][3]};
            if (BIAS) {
                float2 bv = *(const float2*)(bias + col);
                v0.x += bv.x; v0.y += bv.y;
                v1.x += bv.x; v1.y += bv.y;
            }
            *(float2*)(C + (size_t)r0 * N + col)       = v0;
            *(float2*)(C + (size_t)(r0 + 8) * N + col) = v1;
        }
    }
}

// ======================= conversion kernels =================================
__global__ void split_f32(const float* __restrict__ in,
                          __nv_bfloat16* __restrict__ hi,
                          __nv_bfloat16* __restrict__ lo, int n4)
{
    int i = blockIdx.x * blockDim.x + threadIdx.x;
    if (i >= n4) return;
    float4 v = ((const float4*)in)[i];
    __nv_bfloat16 h0 = __float2bfloat16(v.x), h1 = __float2bfloat16(v.y);
    __nv_bfloat16 h2 = __float2bfloat16(v.z), h3 = __float2bfloat16(v.w);
    __nv_bfloat16 l0 = __float2bfloat16(v.x - __bfloat162float(h0));
    __nv_bfloat16 l1 = __float2bfloat16(v.y - __bfloat162float(h1));
    __nv_bfloat16 l2 = __float2bfloat16(v.z - __bfloat162float(h2));
    __nv_bfloat16 l3 = __float2bfloat16(v.w - __bfloat162float(h3));
    ((__nv_bfloat162*)hi)[2 * i]     = __nv_bfloat162(h0, h1);
    ((__nv_bfloat162*)hi)[2 * i + 1] = __nv_bfloat162(h2, h3);
    ((__nv_bfloat162*)lo)[2 * i]     = __nv_bfloat162(l0, l1);
    ((__nv_bfloat162*)lo)[2 * i + 1] = __nv_bfloat162(l2, l3);
}

// w (K,N) fp32 -> wT (N,K) bf16 hi/lo
__global__ void split_wT(const float* __restrict__ w,
                         __nv_bfloat16* __restrict__ thi,
                         __nv_bfloat16* __restrict__ tlo, int K, int N)
{
    __shared__ float t[32][33];
    int bx = blockIdx.x * 32;  // N
    int by = blockIdx.y * 32;  // K
    int tx = threadIdx.x, ty = threadIdx.y;   // (32, 8)
    #pragma unroll
    for (int i = 0; i < 32; i += 8)
        t[ty + i][tx] = w[(size_t)(by + ty + i) * N + bx + tx];
    __syncthreads();
    #pragma unroll
    for (int i = 0; i < 32; i += 8) {
        float v = t[tx][ty + i];
        __nv_bfloat16 h = __float2bfloat16(v);
        __nv_bfloat16 l = __float2bfloat16(v - __bfloat162float(h));
        size_t o = (size_t)(bx + ty + i) * K + by + tx;
        thi[o] = h;
        tlo[o] = l;
    }
}

// ======================= per-head feature projection + elu1 =================
__global__ __launch_bounds__(256) void proj_kernel(const float* __restrict__ proj)
{
    const int z = blockIdx.z;
    const int sel = z & 1;
    const int h = z >> 1;

    __shared__ float Ast[32][132];
    __shared__ float Bs[32][128];

    const int tid = threadIdx.x;
    const int tx = tid & 15, ty = tid >> 4;
    const int rowbase = blockIdx.y * 128;
    const int fbase = blockIdx.x * 128;

    const int aoff = sel * 1024 + h * 64;
    const float* Bg = proj + h * 64 * 256 + fbase;

    float acc[8][8];
    #pragma unroll
    for (int i = 0; i < 8; i++)
        #pragma unroll
        for (int j = 0; j < 8; j++) acc[i][j] = 0.f;

    for (int k0 = 0; k0 < 64; k0 += 32) {
        #pragma unroll
        for (int i = 0; i < 4; i++) {
            int idx = tid + i * 256;
            int row = idx >> 3, c4 = (idx & 7) * 4;
            float4 av = *(const float4*)(
                &g_qkv[(size_t)(rowbase + row) * 3072 + aoff + k0 + c4]);
            Ast[c4 + 0][row] = av.x;
            Ast[c4 + 1][row] = av.y;
            Ast[c4 + 2][row] = av.z;
            Ast[c4 + 3][row] = av.w;
            int brow = idx >> 5, bc4 = (idx & 31) * 4;
            *(float4*)(&Bs[brow][bc4]) =
                *(const float4*)(Bg + (k0 + brow) * 256 + bc4);
        }
        __syncthreads();

        #pragma unroll
        for (int k = 0; k < 32; k++) {
            float4 a0 = *(const float4*)(&Ast[k][ty * 8]);
            float4 a1 = *(const float4*)(&Ast[k][ty * 8 + 4]);
            float4 b0 = *(const float4*)(&Bs[k][tx * 8]);
            float4 b1 = *(const float4*)(&Bs[k][tx * 8 + 4]);
            float ra[8] = {a0.x, a0.y, a0.z, a0.w, a1.x, a1.y, a1.z, a1.w};
            float rb[8] = {b0.x, b0.y, b0.z, b0.w, b1.x, b1.y, b1.z, b1.w};
            #pragma unroll
            for (int i = 0; i < 8; i++)
                #pragma unroll
                for (int j = 0; j < 8; j++)
                    acc[i][j] += ra[i] * rb[j];
        }
        __syncthreads();
    }

    float* out = sel ? g_kproj : g_qproj;
    #pragma unroll
    for (int i = 0; i < 8; i++) {
        int r = rowbase + ty * 8 + i;
        int b = r >> 12, n = r & 4095;
        size_t crow = (((size_t)(b * 16 + h) * 4096 + n) * 256) + fbase + tx * 8;
        float4 o0, o1;
        float v;
        v = acc[i][0]; o0.x = v > 0.f ? v + 1.f : __expf(v);
        v = acc[i][1]; o0.y = v > 0.f ? v + 1.f : __expf(v);
        v = acc[i][2]; o0.z = v > 0.f ? v + 1.f : __expf(v);
        v = acc[i][3]; o0.w = v > 0.f ? v + 1.f : __expf(v);
        v = acc[i][4]; o1.x = v > 0.f ? v + 1.f : __expf(v);
        v = acc[i][5]; o1.y = v > 0.f ? v + 1.f : __expf(v);
        v = acc[i][6]; o1.z = v > 0.f ? v + 1.f : __expf(v);
        v = acc[i][7]; o1.w = v > 0.f ? v + 1.f : __expf(v);
        *(float4*)(&out[crow])     = o0;
        *(float4*)(&out[crow + 4]) = o1;
    }
}

// ======================= kv state + k_sum ===================================
__global__ __launch_bounds__(256) void kv_kernel()
{
    const int bh = blockIdx.y;
    const int b = bh >> 4, h = bh & 15;
    const int fbase = blockIdx.x * 64;

    __shared__ float As[32][64];
    __shared__ float Bs[32][64];

    const int tid = threadIdx.x;
    const int tf = tid >> 4, td = tid & 15;

    float acc[4][4];
    #pragma unroll
    for (int i = 0; i < 4; i++)
        #pragma unroll
        for (int j = 0; j < 4; j++) acc[i][j] = 0.f;
    float ks[4] = {0.f, 0.f, 0.f, 0.f};

    const float* kp = g_kproj + (size_t)bh * 4096 * 256;
    const size_t voff = 2048 + h * 64;

    for (int n0 = 0; n0 < 4096; n0 += 32) {
        #pragma unroll
        for (int i = 0; i < 2; i++) {
            int idx = tid + i * 256;
            int row = idx >> 4, c4 = (idx & 15) * 4;
            *(float4*)(&As[row][c4]) =
                *(const float4*)(kp + (size_t)(n0 + row) * 256 + fbase + c4);
            *(float4*)(&Bs[row][c4]) =
                *(const float4*)(&g_qkv[(size_t)(b * 4096 + n0 + row) * 3072 + voff + c4]);
        }
        __syncthreads();

        #pragma unroll
        for (int n = 0; n < 32; n++) {
            float4 a  = *(const float4*)(&As[n][tf * 4]);
            float4 bv = *(const float4*)(&Bs[n][td * 4]);
            float ra[4] = {a.x, a.y, a.z, a.w};
            float rb[4] = {bv.x, bv.y, bv.z, bv.w};
            #pragma unroll
            for (int i = 0; i < 4; i++) {
                #pragma unroll
                for (int j = 0; j < 4; j++)
                    acc[i][j] += ra[i] * rb[j];
                ks[i] += ra[i];
            }
        }
        __syncthreads();
    }

    #pragma unroll
    for (int i = 0; i < 4; i++) {
        size_t row = (size_t)bh * 256 + fbase + tf * 4 + i;
        float4 o;
        o.x = acc[i][0]; o.y = acc[i][1]; o.z = acc[i][2]; o.w = acc[i][3];
        *(float4*)(&g_kv[row * 64 + td * 4]) = o;
        if (td == 0) g_ksum[row] = ks[i];
    }
}

// ======================= attn + z-norm, emits bf16 hi/lo ====================
__global__ __launch_bounds__(256) void attn_kernel()
{
    const int bh = blockIdx.y;
    const int b = bh >> 4, h = bh & 15;
    const int nbase = blockIdx.x * 128;

    __shared__ float Ast[16][132];
    __shared__ float Bs[16][64];
    __shared__ float kss[16];

    const int tid = threadIdx.x;
    const int tr = tid >> 4, tc = tid & 15;

    float acc[8][4];
    #pragma unroll
    for (int i = 0; i < 8; i++)
        #pragma unroll
        for (int j = 0; j < 4; j++) acc[i][j] = 0.f;
    float zacc[8] = {0.f, 0.f, 0.f, 0.f, 0.f, 0.f, 0.f, 0.f};

    const float* qp = g_qproj + (size_t)bh * 4096 * 256 + (size_t)nbase * 256;
    const float* kvp = g_kv + (size_t)bh * 256 * 64;
    const float* ksp = g_ksum + (size_t)bh * 256;

    for (int k0 = 0; k0 < 256; k0 += 16) {
        #pragma unroll
        for (int i = 0; i < 2; i++) {
            int idx = tid + i * 256;
            int row = idx >> 2, c4 = (idx & 3) * 4;
            float4 av = *(const float4*)(qp + (size_t)row * 256 + k0 + c4);
            Ast[c4 + 0][row] = av.x;
            Ast[c4 + 1][row] = av.y;
            Ast[c4 + 2][row] = av.z;
            Ast[c4 + 3][row] = av.w;
        }
        {
            int row = tid >> 4, c4 = (tid & 15) * 4;
            *(float4*)(&Bs[row][c4]) = *(const float4*)(kvp + (k0 + row) * 64 + c4);
        }
        if (tid < 16) kss[tid] = ksp[k0 + tid];
        __syncthreads();

        #pragma unroll
        for (int k = 0; k < 16; k++) {
            float4 a0 = *(const float4*)(&Ast[k][tr * 8]);
            float4 a1 = *(const float4*)(&Ast[k][tr * 8 + 4]);
            float4 bv = *(const float4*)(&Bs[k][tc * 4]);
            float ra[8] = {a0.x, a0.y, a0.z, a0.w, a1.x, a1.y, a1.z, a1.w};
            float rb[4] = {bv.x, bv.y, bv.z, bv.w};
            float kk = kss[k];
            #pragma unroll
            for (int i = 0; i < 8; i++) {
                #pragma unroll
                for (int j = 0; j < 4; j++)
                    acc[i][j] += ra[i] * rb[j];
                zacc[i] += ra[i] * kk;
            }
        }
        __syncthreads();
    }

    #pragma unroll
    for (int i = 0; i < 8; i++) {
        int r = tr * 8 + i;
        float zi = 1.0f / (zacc[i] + 1e-8f);
        float v0 = acc[i][0] * zi, v1 = acc[i][1] * zi;
        float v2 = acc[i][2] * zi, v3 = acc[i][3] * zi;
        size_t base = (size_t)(b * 4096 + nbase + r) * 1024 + h * 64 + tc * 4;
        __nv_bfloat16 h0 = __float2bfloat16(v0), h1 = __float2bfloat16(v1);
        __nv_bfloat16 h2 = __float2bfloat16(v2), h3 = __float2bfloat16(v3);
        ((__nv_bfloat162*)(g_attn_hi + base))[0] = __nv_bfloat162(h0, h1);
        ((__nv_bfloat162*)(g_attn_hi + base))[1] = __nv_bfloat162(h2, h3);
        __nv_bfloat16 l0 = __float2bfloat16(v0 - __bfloat162float(h0));
        __nv_bfloat16 l1 = __float2bfloat16(v1 - __bfloat162float(h1));
        __nv_bfloat16 l2 = __float2bfloat16(v2 - __bfloat162float(h2));
        __nv_bfloat16 l3 = __float2bfloat16(v3 - __bfloat162float(h3));
        ((__nv_bfloat162*)(g_attn_lo + base))[0] = __nv_bfloat162(l0, l1);
        ((__nv_bfloat162*)(g_attn_lo + base))[1] = __nv_bfloat162(l2, l3);
    }
}

// ===========================================================================
extern "C" void kernel_launch(void* const* d_in, const int* in_sizes, int n_in,
                              void* d_out, int out_size)
{
    const float* x      = (const float*)d_in[0];  // (4,4096,1024)
    const float* w_qkv  = (const float*)d_in[1];  // (1024,3072)
    const float* proj   = (const float*)d_in[2];  // (16,64,256)
    const float* w_out  = (const float*)d_in[3];  // (1024,1024)
    const float* b_out  = (const float*)d_in[4];  // (1024,)
    float* out = (float*)d_out;                   // (4,4096,1024)

    cudaFuncSetAttribute(hmma_gemm<false>,
                         cudaFuncAttributeMaxDynamicSharedMemorySize, GEMM_SMEM);
    cudaFuncSetAttribute(hmma_gemm<true>,
                         cudaFuncAttributeMaxDynamicSharedMemorySize, GEMM_SMEM);

    float* qkv_p;
    __nv_bfloat16 *xhi, *xlo, *wqh, *wql, *woh, *wol, *ahi, *alo;
    cudaGetSymbolAddress((void**)&qkv_p, g_qkv);
    cudaGetSymbolAddress((void**)&xhi, g_xhi);
    cudaGetSymbolAddress((void**)&xlo, g_xlo);
    cudaGetSymbolAddress((void**)&wqh, g_wqkvT_hi);
    cudaGetSymbolAddress((void**)&wql, g_wqkvT_lo);
    cudaGetSymbolAddress((void**)&woh, g_woutT_hi);
    cudaGetSymbolAddress((void**)&wol, g_woutT_lo);
    cudaGetSymbolAddress((void**)&ahi, g_attn_hi);
    cudaGetSymbolAddress((void**)&alo, g_attn_lo);

    // 0) conversions: x split; weight transposed splits
    split_f32<<<16384, 256>>>(x, xhi, xlo, 16777216 / 4);
    split_wT<<<dim3(96, 32), dim3(32, 8)>>>(w_qkv, wqh, wql, 1024, 3072);
    split_wT<<<dim3(32, 32), dim3(32, 8)>>>(w_out, woh, wol, 1024, 1024);

    // 1) qkv = x @ w_qkv  (HMMA, bf16x3)
    hmma_gemm<false><<<dim3(24, 128), 256, GEMM_SMEM>>>(
        xhi, xlo, wqh, wql, nullptr, qkv_p, 3072, 1024);

    // 2) q_proj / k_proj = elu1(head-slice @ proj[h])
    proj_kernel<<<dim3(2, 128, 32), 256>>>(proj);
    // 3) kv state + k_sum
    kv_kernel<<<dim3(4, 64), 256>>>();
    // 4) attn + z normalization -> bf16 hi/lo
    attn_kernel<<<dim3(32, 64), 256>>>();

    // 5) out = attn @ w_out + b_out  (HMMA, bf16x3)
    hmma_gemm<true><<<dim3(8, 128), 256, GEMM_SMEM>>>(
        ahi, alo, woh, wol, b_out, out, 1024, 1024);
}

// round 4
// speedup vs baseline: 1.8217x; 1.0651x over previous
#include <cuda_runtime.h>
#include <cuda_bf16.h>
#include <cstdint>

// ======================= device scratch (no allocs) =========================
__device__ float g_qkv[50331648];                 // (16384, 3072)
__device__ float g_qproj[67108864];               // (4,16,4096,256)
__device__ float g_kproj[67108864];
__device__ float g_kv[1048576];                   // (4,16,256,64)
__device__ float g_ksum[16384];                   // (4,16,256)
__device__ __nv_bfloat16 g_xhi[16777216];         // x split (16384,1024)
__device__ __nv_bfloat16 g_xlo[16777216];
__device__ __nv_bfloat16 g_wqkvT_hi[3145728];     // w_qkv^T (3072,1024)
__device__ __nv_bfloat16 g_wqkvT_lo[3145728];
__device__ __nv_bfloat16 g_woutT_hi[1048576];     // w_out^T (1024,1024)
__device__ __nv_bfloat16 g_woutT_lo[1048576];
__device__ __nv_bfloat16 g_attn_hi[16777216];     // attn (16384,1024) split
__device__ __nv_bfloat16 g_attn_lo[16777216];

// ======================= PTX helpers (baseline ISA only) ====================
__device__ __forceinline__ uint32_t smem_u32(const void* p) {
    uint32_t a;
    asm("{ .reg .u64 t; cvta.to.shared.u64 t, %1; cvt.u32.u64 %0, t; }"
        : "=r"(a) : "l"(p));
    return a;
}
__device__ __forceinline__ void cp16(uint32_t saddr, const void* g) {
    asm volatile("cp.async.cg.shared.global [%0], [%1], 16;"
                 :: "r"(saddr), "l"(g) : "memory");
}
#define CP_COMMIT() asm volatile("cp.async.commit_group;" ::: "memory")
#define CP_WAIT1()  asm volatile("cp.async.wait_group 1;" ::: "memory")
#define CP_WAIT0()  asm volatile("cp.async.wait_group 0;" ::: "memory")

__device__ __forceinline__ void ldsm4(uint32_t& r0, uint32_t& r1,
                                      uint32_t& r2, uint32_t& r3, uint32_t a) {
    asm volatile("ldmatrix.sync.aligned.m8n8.x4.shared.b16 {%0,%1,%2,%3}, [%4];"
                 : "=r"(r0), "=r"(r1), "=r"(r2), "=r"(r3) : "r"(a));
}
__device__ __forceinline__ void mma16816(float* c, const uint32_t* a,
                                         const uint32_t* b) {
    asm volatile(
        "mma.sync.aligned.m16n8k16.row.col.f32.bf16.bf16.f32 "
        "{%0,%1,%2,%3}, {%4,%5,%6,%7}, {%8,%9}, {%0,%1,%2,%3};"
        : "+f"(c[0]), "+f"(c[1]), "+f"(c[2]), "+f"(c[3])
        : "r"(a[0]), "r"(a[1]), "r"(a[2]), "r"(a[3]), "r"(b[0]), "r"(b[1]));
}

// ======================= HMMA GEMM ==========================================
// C(M,N) = (Ahi+Alo)(M,K) @ (Bhi+Blo)(N,K)^T [+ bias], fp32 out.
// 3-term split. 128x64x32 CTA tile, 8 warps (4 M x 2 N), 32x32 warp tile.
// 2 stages x 55296B = 110592B smem -> 2 CTAs/SM for latency hiding.
static constexpr int PITCH_B  = 144;                // bytes per 32-elem k row
static constexpr int A_TILE_B = 128 * PITCH_B;      // 18432
static constexpr int B_TILE_B = 64 * PITCH_B;       // 9216
static constexpr int STAGE_B  = 2 * A_TILE_B + 2 * B_TILE_B;   // 55296
static constexpr int GEMM_SMEM = 2 * STAGE_B;       // 110592

template<bool BIAS>
__global__ __launch_bounds__(256, 2) void hmma_gemm(
    const __nv_bfloat16* __restrict__ Ahi, const __nv_bfloat16* __restrict__ Alo,
    const __nv_bfloat16* __restrict__ Bhi, const __nv_bfloat16* __restrict__ Blo,
    const float* __restrict__ bias, float* __restrict__ C, int N, int K)
{
    extern __shared__ char smem[];
    const uint32_t sbase = smem_u32(smem);
    const int tid = threadIdx.x;
    const int wid = tid >> 5, lane = tid & 31;
    const int warpM = wid & 3, warpN = wid >> 2;
    const int m0 = blockIdx.y * 128;
    const int n0 = blockIdx.x * 64;

    float acc[2][4][4];
    #pragma unroll
    for (int i = 0; i < 2; i++)
        #pragma unroll
        for (int j = 0; j < 4; j++)
            #pragma unroll
            for (int q = 0; q < 4; q++) acc[i][j][q] = 0.f;

    const int NC = K >> 5;   // BK = 32

    // stage loader: (Ah,Al: 128 rows) + (Bh,Bl: 64 rows) x 4 chunks of 16B
    // = 1536 cp.async -> 6 per thread
    auto load_stage = [&](int c, int s) {
        const uint32_t sb = sbase + s * STAGE_B;
        #pragma unroll
        for (int i = 0; i < 6; i++) {
            int idx = tid + i * 256;
            int rc = idx >> 2, ch = idx & 3;
            uint32_t dst;
            const __nv_bfloat16* g;
            if (rc < 128)      { dst = sb + rc * PITCH_B;
                                 g = Ahi + (size_t)(m0 + rc) * K; }
            else if (rc < 256) { dst = sb + A_TILE_B + (rc - 128) * PITCH_B;
                                 g = Alo + (size_t)(m0 + rc - 128) * K; }
            else if (rc < 320) { dst = sb + 2 * A_TILE_B + (rc - 256) * PITCH_B;
                                 g = Bhi + (size_t)(n0 + rc - 256) * K; }
            else               { dst = sb + 2 * A_TILE_B + B_TILE_B + (rc - 320) * PITCH_B;
                                 g = Blo + (size_t)(n0 + rc - 320) * K; }
            cp16(dst + ch * 16, g + c * 32 + ch * 8);
        }
        CP_COMMIT();
    };

    load_stage(0, 0);

    for (int c = 0; c < NC; c++) {
        const int s = c & 1;
        if (c + 1 < NC) { load_stage(c + 1, s ^ 1); CP_WAIT1(); }
        else            { CP_WAIT0(); }
        __syncthreads();

        const uint32_t sb = sbase + s * STAGE_B;
        const uint32_t Ah = sb, Al = sb + A_TILE_B;
        const uint32_t Bh = sb + 2 * A_TILE_B, Bl = sb + 2 * A_TILE_B + B_TILE_B;

        // load ALL fragments for both k16 steps up front (batch ldmatrix)
        uint32_t ahi[2][2][4], alo[2][2][4], bhi[2][4][2], blo[2][4][2];
        #pragma unroll
        for (int ks = 0; ks < 2; ks++) {
            #pragma unroll
            for (int mt = 0; mt < 2; mt++) {
                int r = warpM * 32 + mt * 16 + (lane & 15);
                uint32_t off = r * PITCH_B + (ks * 2 + (lane >> 4)) * 16;
                ldsm4(ahi[ks][mt][0], ahi[ks][mt][1], ahi[ks][mt][2], ahi[ks][mt][3], Ah + off);
                ldsm4(alo[ks][mt][0], alo[ks][mt][1], alo[ks][mt][2], alo[ks][mt][3], Al + off);
            }
            #pragma unroll
            for (int tp = 0; tp < 2; tp++) {
                int nr = warpN * 32 + tp * 16 + ((lane >> 4) << 3) + (lane & 7);
                uint32_t off = nr * PITCH_B + (ks * 2 + ((lane >> 3) & 1)) * 16;
                ldsm4(bhi[ks][2 * tp][0], bhi[ks][2 * tp][1],
                      bhi[ks][2 * tp + 1][0], bhi[ks][2 * tp + 1][1], Bh + off);
                ldsm4(blo[ks][2 * tp][0], blo[ks][2 * tp][1],
                      blo[ks][2 * tp + 1][0], blo[ks][2 * tp + 1][1], Bl + off);
            }
        }
        #pragma unroll
        for (int ks = 0; ks < 2; ks++)
            #pragma unroll
            for (int mt = 0; mt < 2; mt++)
                #pragma unroll
                for (int nt = 0; nt < 4; nt++) {
                    mma16816(acc[mt][nt], ahi[ks][mt], bhi[ks][nt]);
                    mma16816(acc[mt][nt], ahi[ks][mt], blo[ks][nt]);
                    mma16816(acc[mt][nt], alo[ks][mt], bhi[ks][nt]);
                }
        __syncthreads();
    }

    // --- epilogue ---
    #pragma unroll
    for (int mt = 0; mt < 2; mt++) {
        int r0 = m0 + warpM * 32 + mt * 16 + (lane >> 2);
        #pragma unroll
        for (int nt = 0; nt < 4; nt++) {
            int col = n0 + warpN * 32 + nt * 8 + (lane & 3) * 2;
            float2 v0 = {acc[mt][nt][0], acc[mt][nt][1]};
            float2 v1 = {acc[mt][nt][2], acc[mt][nt][3]};
            if (BIAS) {
                float2 bv = *(const float2*)(bias + col);
                v0.x += bv.x; v0.y += bv.y;
                v1.x += bv.x; v1.y += bv.y;
            }
            *(float2*)(C + (size_t)r0 * N + col)       = v0;
            *(float2*)(C + (size_t)(r0 + 8) * N + col) = v1;
        }
    }
}

// ======================= conversion kernels =================================
__global__ void split_f32(const float* __restrict__ in,
                          __nv_bfloat16* __restrict__ hi,
                          __nv_bfloat16* __restrict__ lo, int n4)
{
    int i = blockIdx.x * blockDim.x + threadIdx.x;
    if (i >= n4) return;
    float4 v = ((const float4*)in)[i];
    __nv_bfloat16 h0 = __float2bfloat16(v.x), h1 = __float2bfloat16(v.y);
    __nv_bfloat16 h2 = __float2bfloat16(v.z), h3 = __float2bfloat16(v.w);
    __nv_bfloat16 l0 = __float2bfloat16(v.x - __bfloat162float(h0));
    __nv_bfloat16 l1 = __float2bfloat16(v.y - __bfloat162float(h1));
    __nv_bfloat16 l2 = __float2bfloat16(v.z - __bfloat162float(h2));
    __nv_bfloat16 l3 = __float2bfloat16(v.w - __bfloat162float(h3));
    ((__nv_bfloat162*)hi)[2 * i]     = __nv_bfloat162(h0, h1);
    ((__nv_bfloat162*)hi)[2 * i + 1] = __nv_bfloat162(h2, h3);
    ((__nv_bfloat162*)lo)[2 * i]     = __nv_bfloat162(l0, l1);
    ((__nv_bfloat162*)lo)[2 * i + 1] = __nv_bfloat162(l2, l3);
}

// w (K,N) fp32 -> wT (N,K) bf16 hi/lo
__global__ void split_wT(const float* __restrict__ w,
                         __nv_bfloat16* __restrict__ thi,
                         __nv_bfloat16* __restrict__ tlo, int K, int N)
{
    __shared__ float t[32][33];
    int bx = blockIdx.x * 32;  // N
    int by = blockIdx.y * 32;  // K
    int tx = threadIdx.x, ty = threadIdx.y;   // (32, 8)
    #pragma unroll
    for (int i = 0; i < 32; i += 8)
        t[ty + i][tx] = w[(size_t)(by + ty + i) * N + bx + tx];
    __syncthreads();
    #pragma unroll
    for (int i = 0; i < 32; i += 8) {
        float v = t[tx][ty + i];
        __nv_bfloat16 h = __float2bfloat16(v);
        __nv_bfloat16 l = __float2bfloat16(v - __bfloat162float(h));
        size_t o = (size_t)(bx + ty + i) * K + by + tx;
        thi[o] = h;
        tlo[o] = l;
    }
}

// ======================= per-head feature projection + elu1 =================
__global__ __launch_bounds__(256) void proj_kernel(const float* __restrict__ proj)
{
    const int z = blockIdx.z;
    const int sel = z & 1;
    const int h = z >> 1;

    __shared__ float Ast[32][132];
    __shared__ float Bs[32][128];

    const int tid = threadIdx.x;
    const int tx = tid & 15, ty = tid >> 4;
    const int rowbase = blockIdx.y * 128;
    const int fbase = blockIdx.x * 128;

    const int aoff = sel * 1024 + h * 64;
    const float* Bg = proj + h * 64 * 256 + fbase;

    float acc[8][8];
    #pragma unroll
    for (int i = 0; i < 8; i++)
        #pragma unroll
        for (int j = 0; j < 8; j++) acc[i][j] = 0.f;

    for (int k0 = 0; k0 < 64; k0 += 32) {
        #pragma unroll
        for (int i = 0; i < 4; i++) {
            int idx = tid + i * 256;
            int row = idx >> 3, c4 = (idx & 7) * 4;
            float4 av = *(const float4*)(
                &g_qkv[(size_t)(rowbase + row) * 3072 + aoff + k0 + c4]);
            Ast[c4 + 0][row] = av.x;
            Ast[c4 + 1][row] = av.y;
            Ast[c4 + 2][row] = av.z;
            Ast[c4 + 3][row] = av.w;
            int brow = idx >> 5, bc4 = (idx & 31) * 4;
            *(float4*)(&Bs[brow][bc4]) =
                *(const float4*)(Bg + (k0 + brow) * 256 + bc4);
        }
        __syncthreads();

        #pragma unroll
        for (int k = 0; k < 32; k++) {
            float4 a0 = *(const float4*)(&Ast[k][ty * 8]);
            float4 a1 = *(const float4*)(&Ast[k][ty * 8 + 4]);
            float4 b0 = *(const float4*)(&Bs[k][tx * 8]);
            float4 b1 = *(const float4*)(&Bs[k][tx * 8 + 4]);
            float ra[8] = {a0.x, a0.y, a0.z, a0.w, a1.x, a1.y, a1.z, a1.w};
            float rb[8] = {b0.x, b0.y, b0.z, b0.w, b1.x, b1.y, b1.z, b1.w};
            #pragma unroll
            for (int i = 0; i < 8; i++)
                #pragma unroll
                for (int j = 0; j < 8; j++)
                    acc[i][j] += ra[i] * rb[j];
        }
        __syncthreads();
    }

    float* out = sel ? g_kproj : g_qproj;
    #pragma unroll
    for (int i = 0; i < 8; i++) {
        int r = rowbase + ty * 8 + i;
        int b = r >> 12, n = r & 4095;
        size_t crow = (((size_t)(b * 16 + h) * 4096 + n) * 256) + fbase + tx * 8;
        float4 o0, o1;
        float v;
        v = acc[i][0]; o0.x = v > 0.f ? v + 1.f : __expf(v);
        v = acc[i][1]; o0.y = v > 0.f ? v + 1.f : __expf(v);
        v = acc[i][2]; o0.z = v > 0.f ? v + 1.f : __expf(v);
        v = acc[i][3]; o0.w = v > 0.f ? v + 1.f : __expf(v);
        v = acc[i][4]; o1.x = v > 0.f ? v + 1.f : __expf(v);
        v = acc[i][5]; o1.y = v > 0.f ? v + 1.f : __expf(v);
        v = acc[i][6]; o1.z = v > 0.f ? v + 1.f : __expf(v);
        v = acc[i][7]; o1.w = v > 0.f ? v + 1.f : __expf(v);
        *(float4*)(&out[crow])     = o0;
        *(float4*)(&out[crow + 4]) = o1;
    }
}

// ======================= kv state + k_sum ===================================
__global__ __launch_bounds__(256) void kv_kernel()
{
    const int bh = blockIdx.y;
    const int b = bh >> 4, h = bh & 15;
    const int fbase = blockIdx.x * 64;

    __shared__ float As[32][64];
    __shared__ float Bs[32][64];

    const int tid = threadIdx.x;
    const int tf = tid >> 4, td = tid & 15;

    float acc[4][4];
    #pragma unroll
    for (int i = 0; i < 4; i++)
        #pragma unroll
        for (int j = 0; j < 4; j++) acc[i][j] = 0.f;
    float ks[4] = {0.f, 0.f, 0.f, 0.f};

    const float* kp = g_kproj + (size_t)bh * 4096 * 256;
    const size_t voff = 2048 + h * 64;

    for (int n0 = 0; n0 < 4096; n0 += 32) {
        #pragma unroll
        for (int i = 0; i < 2; i++) {
            int idx = tid + i * 256;
            int row = idx >> 4, c4 = (idx & 15) * 4;
            *(float4*)(&As[row][c4]) =
                *(const float4*)(kp + (size_t)(n0 + row) * 256 + fbase + c4);
            *(float4*)(&Bs[row][c4]) =
                *(const float4*)(&g_qkv[(size_t)(b * 4096 + n0 + row) * 3072 + voff + c4]);
        }
        __syncthreads();

        #pragma unroll
        for (int n = 0; n < 32; n++) {
            float4 a  = *(const float4*)(&As[n][tf * 4]);
            float4 bv = *(const float4*)(&Bs[n][td * 4]);
            float ra[4] = {a.x, a.y, a.z, a.w};
            float rb[4] = {bv.x, bv.y, bv.z, bv.w};
            #pragma unroll
            for (int i = 0; i < 4; i++) {
                #pragma unroll
                for (int j = 0; j < 4; j++)
                    acc[i][j] += ra[i] * rb[j];
                ks[i] += ra[i];
            }
        }
        __syncthreads();
    }

    #pragma unroll
    for (int i = 0; i < 4; i++) {
        size_t row = (size_t)bh * 256 + fbase + tf * 4 + i;
        float4 o;
        o.x = acc[i][0]; o.y = acc[i][1]; o.z = acc[i][2]; o.w = acc[i][3];
        *(float4*)(&g_kv[row * 64 + td * 4]) = o;
        if (td == 0) g_ksum[row] = ks[i];
    }
}

// ======================= attn + z-norm, emits bf16 hi/lo ====================
__global__ __launch_bounds__(256) void attn_kernel()
{
    const int bh = blockIdx.y;
    const int b = bh >> 4, h = bh & 15;
    const int nbase = blockIdx.x * 128;

    __shared__ float Ast[16][132];
    __shared__ float Bs[16][64];
    __shared__ float kss[16];

    const int tid = threadIdx.x;
    const int tr = tid >> 4, tc = tid & 15;

    float acc[8][4];
    #pragma unroll
    for (int i = 0; i < 8; i++)
        #pragma unroll
        for (int j = 0; j < 4; j++) acc[i][j] = 0.f;
    float zacc[8] = {0.f, 0.f, 0.f, 0.f, 0.f, 0.f, 0.f, 0.f};

    const float* qp = g_qproj + (size_t)bh * 4096 * 256 + (size_t)nbase * 256;
    const float* kvp = g_kv + (size_t)bh * 256 * 64;
    const float* ksp = g_ksum + (size_t)bh * 256;

    for (int k0 = 0; k0 < 256; k0 += 16) {
        #pragma unroll
        for (int i = 0; i < 2; i++) {
            int idx = tid + i * 256;
            int row = idx >> 2, c4 = (idx & 3) * 4;
            float4 av = *(const float4*)(qp + (size_t)row * 256 + k0 + c4);
            Ast[c4 + 0][row] = av.x;
            Ast[c4 + 1][row] = av.y;
            Ast[c4 + 2][row] = av.z;
            Ast[c4 + 3][row] = av.w;
        }
        {
            int row = tid >> 4, c4 = (tid & 15) * 4;
            *(float4*)(&Bs[row][c4]) = *(const float4*)(kvp + (k0 + row) * 64 + c4);
        }
        if (tid < 16) kss[tid] = ksp[k0 + tid];
        __syncthreads();

        #pragma unroll
        for (int k = 0; k < 16; k++) {
            float4 a0 = *(const float4*)(&Ast[k][tr * 8]);
            float4 a1 = *(const float4*)(&Ast[k][tr * 8 + 4]);
            float4 bv = *(const float4*)(&Bs[k][tc * 4]);
            float ra[8] = {a0.x, a0.y, a0.z, a0.w, a1.x, a1.y, a1.z, a1.w};
            float rb[4] = {bv.x, bv.y, bv.z, bv.w};
            float kk = kss[k];
            #pragma unroll
            for (int i = 0; i < 8; i++) {
                #pragma unroll
                for (int j = 0; j < 4; j++)
                    acc[i][j] += ra[i] * rb[j];
                zacc[i] += ra[i] * kk;
            }
        }
        __syncthreads();
    }

    #pragma unroll
    for (int i = 0; i < 8; i++) {
        int r = tr * 8 + i;
        float zi = 1.0f / (zacc[i] + 1e-8f);
        float v0 = acc[i][0] * zi, v1 = acc[i][1] * zi;
        float v2 = acc[i][2] * zi, v3 = acc[i][3] * zi;
        size_t base = (size_t)(b * 4096 + nbase + r) * 1024 + h * 64 + tc * 4;
        __nv_bfloat16 h0 = __float2bfloat16(v0), h1 = __float2bfloat16(v1);
        __nv_bfloat16 h2 = __float2bfloat16(v2), h3 = __float2bfloat16(v3);
        ((__nv_bfloat162*)(g_attn_hi + base))[0] = __nv_bfloat162(h0, h1);
        ((__nv_bfloat162*)(g_attn_hi + base))[1] = __nv_bfloat162(h2, h3);
        __nv_bfloat16 l0 = __float2bfloat16(v0 - __bfloat162float(h0));
        __nv_bfloat16 l1 = __float2bfloat16(v1 - __bfloat162float(h1));
        __nv_bfloat16 l2 = __float2bfloat16(v2 - __bfloat162float(h2));
        __nv_bfloat16 l3 = __float2bfloat16(v3 - __bfloat162float(h3));
        ((__nv_bfloat162*)(g_attn_lo + base))[0] = __nv_bfloat162(l0, l1);
        ((__nv_bfloat162*)(g_attn_lo + base))[1] = __nv_bfloat162(l2, l3);
    }
}

// ===========================================================================
extern "C" void kernel_launch(void* const* d_in, const int* in_sizes, int n_in,
                              void* d_out, int out_size)
{
    const float* x      = (const float*)d_in[0];  // (4,4096,1024)
    const float* w_qkv  = (const float*)d_in[1];  // (1024,3072)
    const float* proj   = (const float*)d_in[2];  // (16,64,256)
    const float* w_out  = (const float*)d_in[3];  // (1024,1024)
    const float* b_out  = (const float*)d_in[4];  // (1024,)
    float* out = (float*)d_out;                   // (4,4096,1024)

    cudaFuncSetAttribute(hmma_gemm<false>,
                         cudaFuncAttributeMaxDynamicSharedMemorySize, GEMM_SMEM);
    cudaFuncSetAttribute(hmma_gemm<true>,
                         cudaFuncAttributeMaxDynamicSharedMemorySize, GEMM_SMEM);

    float* qkv_p;
    __nv_bfloat16 *xhi, *xlo, *wqh, *wql, *woh, *wol, *ahi, *alo;
    cudaGetSymbolAddress((void**)&qkv_p, g_qkv);
    cudaGetSymbolAddress((void**)&xhi, g_xhi);
    cudaGetSymbolAddress((void**)&xlo, g_xlo);
    cudaGetSymbolAddress((void**)&wqh, g_wqkvT_hi);
    cudaGetSymbolAddress((void**)&wql, g_wqkvT_lo);
    cudaGetSymbolAddress((void**)&woh, g_woutT_hi);
    cudaGetSymbolAddress((void**)&wol, g_woutT_lo);
    cudaGetSymbolAddress((void**)&ahi, g_attn_hi);
    cudaGetSymbolAddress((void**)&alo, g_attn_lo);

    // 0) conversions: x split; weight transposed splits
    split_f32<<<16384, 256>>>(x, xhi, xlo, 16777216 / 4);
    split_wT<<<dim3(96, 32), dim3(32, 8)>>>(w_qkv, wqh, wql, 1024, 3072);
    split_wT<<<dim3(32, 32), dim3(32, 8)>>>(w_out, woh, wol, 1024, 1024);

    // 1) qkv = x @ w_qkv  (HMMA, bf16x3)
    hmma_gemm<false><<<dim3(48, 128), 256, GEMM_SMEM>>>(
        xhi, xlo, wqh, wql, nullptr, qkv_p, 3072, 1024);

    // 2) q_proj / k_proj = elu1(head-slice @ proj[h])
    proj_kernel<<<dim3(2, 128, 32), 256>>>(proj);
    // 3) kv state + k_sum
    kv_kernel<<<dim3(4, 64), 256>>>();
    // 4) attn + z normalization -> bf16 hi/lo
    attn_kernel<<<dim3(32, 64), 256>>>();

    // 5) out = attn @ w_out + b_out  (HMMA, bf16x3)
    hmma_gemm<true><<<dim3(16, 128), 256, GEMM_SMEM>>>(
        ahi, alo, woh, wol, b_out, out, 1024, 1024);
}

// round 5
// speedup vs baseline: 2.2117x; 1.2141x over previous
#include <cuda_runtime.h>
#include <cuda_bf16.h>
#include <cstdint>

typedef __nv_bfloat16 bf16;
typedef __nv_bfloat162 bf162;

// ======================= device scratch (no allocs) =========================
__device__ bf16 g_qkvh[50331648];     // qkv (16384,3072) hi
__device__ bf16 g_qkvl[50331648];     // lo
__device__ bf16 g_qph[67108864];      // qproj (4,16,4096,256) hi
__device__ bf16 g_qpl[67108864];
__device__ bf16 g_kph[67108864];      // kproj
__device__ bf16 g_kpl[67108864];
__device__ float g_kvpart[4194304];   // kv partials (4 ksplit,64 bh,64 d,256 f)
__device__ float g_kspart[524288];    // ksum partials (128 rowtile,16 h,256 f)
__device__ bf16 g_kvTh[1310720];      // kvT+ksum (64 bh, 80 rows, 256 f)
__device__ bf16 g_kvTl[1310720];
__device__ bf16 g_attn_hi[16777216];  // attn (16384,1024)
__device__ bf16 g_attn_lo[16777216];
__device__ bf16 g_xhi[16777216];      // x split (16384,1024)
__device__ bf16 g_xlo[16777216];
__device__ bf16 g_wqkvT_hi[3145728];  // w_qkv^T (3072,1024)
__device__ bf16 g_wqkvT_lo[3145728];
__device__ bf16 g_woutT_hi[1048576];  // w_out^T (1024,1024)
__device__ bf16 g_woutT_lo[1048576];
__device__ bf16 g_projT_hi[262144];   // projT (16,256,64)
__device__ bf16 g_projT_lo[262144];

// ======================= PTX helpers ========================================
__device__ __forceinline__ uint32_t smem_u32(const void* p) {
    uint32_t a;
    asm("{ .reg .u64 t; cvta.to.shared.u64 t, %1; cvt.u32.u64 %0, t; }"
        : "=r"(a) : "l"(p));
    return a;
}
__device__ __forceinline__ void cp16(uint32_t saddr, const void* g) {
    asm volatile("cp.async.cg.shared.global [%0], [%1], 16;"
                 :: "r"(saddr), "l"(g) : "memory");
}
#define CP_COMMIT() asm volatile("cp.async.commit_group;" ::: "memory")
#define CP_WAIT1()  asm volatile("cp.async.wait_group 1;" ::: "memory")
#define CP_WAIT0()  asm volatile("cp.async.wait_group 0;" ::: "memory")

__device__ __forceinline__ void ldsm4(uint32_t& r0, uint32_t& r1,
                                      uint32_t& r2, uint32_t& r3, uint32_t a) {
    asm volatile("ldmatrix.sync.aligned.m8n8.x4.shared.b16 {%0,%1,%2,%3}, [%4];"
                 : "=r"(r0), "=r"(r1), "=r"(r2), "=r"(r3) : "r"(a));
}
__device__ __forceinline__ void ldsm4t(uint32_t& r0, uint32_t& r1,
                                       uint32_t& r2, uint32_t& r3, uint32_t a) {
    asm volatile("ldmatrix.sync.aligned.m8n8.x4.trans.shared.b16 {%0,%1,%2,%3}, [%4];"
                 : "=r"(r0), "=r"(r1), "=r"(r2), "=r"(r3) : "r"(a));
}
__device__ __forceinline__ void ldsm2(uint32_t& r0, uint32_t& r1, uint32_t a) {
    asm volatile("ldmatrix.sync.aligned.m8n8.x2.shared.b16 {%0,%1}, [%2];"
                 : "=r"(r0), "=r"(r1) : "r"(a));
}
__device__ __forceinline__ void mma16816(float* c, const uint32_t* a,
                                         const uint32_t* b) {
    asm volatile(
        "mma.sync.aligned.m16n8k16.row.col.f32.bf16.bf16.f32 "
        "{%0,%1,%2,%3}, {%4,%5,%6,%7}, {%8,%9}, {%0,%1,%2,%3};"
        : "+f"(c[0]), "+f"(c[1]), "+f"(c[2]), "+f"(c[3])
        : "r"(a[0]), "r"(a[1]), "r"(a[2]), "r"(a[3]), "r"(b[0]), "r"(b[1]));
}
__device__ __forceinline__ void split2(float v, bf16& h, bf16& l) {
    h = __float2bfloat16(v);
    l = __float2bfloat16(v - __bfloat162float(h));
}

// ======================= big HMMA GEMM (qkv / out) ==========================
static constexpr int PITCH_B  = 144;
static constexpr int A_TILE_B = 128 * PITCH_B;
static constexpr int B_TILE_B = 64 * PITCH_B;
static constexpr int STAGE_B  = 2 * A_TILE_B + 2 * B_TILE_B;   // 55296
static constexpr int GEMM_SMEM = 2 * STAGE_B;                  // 110592

template<bool BIAS, bool SPLITOUT>
__global__ __launch_bounds__(256, 2) void hmma_gemm(
    const bf16* __restrict__ Ahi, const bf16* __restrict__ Alo,
    const bf16* __restrict__ Bhi, const bf16* __restrict__ Blo,
    const float* __restrict__ bias, float* __restrict__ C,
    bf16* __restrict__ Chi, bf16* __restrict__ Clo, int N, int K)
{
    extern __shared__ char smem[];
    const uint32_t sbase = smem_u32(smem);
    const int tid = threadIdx.x;
    const int wid = tid >> 5, lane = tid & 31;
    const int warpM = wid & 3, warpN = wid >> 2;
    const int m0 = blockIdx.y * 128;
    const int n0 = blockIdx.x * 64;

    float acc[2][4][4];
    #pragma unroll
    for (int i = 0; i < 2; i++)
        #pragma unroll
        for (int j = 0; j < 4; j++)
            #pragma unroll
            for (int q = 0; q < 4; q++) acc[i][j][q] = 0.f;

    const int NC = K >> 5;

    auto load_stage = [&](int c, int s) {
        const uint32_t sb = sbase + s * STAGE_B;
        #pragma unroll
        for (int i = 0; i < 6; i++) {
            int idx = tid + i * 256;
            int rc = idx >> 2, ch = idx & 3;
            uint32_t dst;
            const bf16* g;
            if (rc < 128)      { dst = sb + rc * PITCH_B;
                                 g = Ahi + (size_t)(m0 + rc) * K; }
            else if (rc < 256) { dst = sb + A_TILE_B + (rc - 128) * PITCH_B;
                                 g = Alo + (size_t)(m0 + rc - 128) * K; }
            else if (rc < 320) { dst = sb + 2 * A_TILE_B + (rc - 256) * PITCH_B;
                                 g = Bhi + (size_t)(n0 + rc - 256) * K; }
            else               { dst = sb + 2 * A_TILE_B + B_TILE_B + (rc - 320) * PITCH_B;
                                 g = Blo + (size_t)(n0 + rc - 320) * K; }
            cp16(dst + ch * 16, g + c * 32 + ch * 8);
        }
        CP_COMMIT();
    };

    load_stage(0, 0);

    for (int c = 0; c < NC; c++) {
        const int s = c & 1;
        if (c + 1 < NC) { load_stage(c + 1, s ^ 1); CP_WAIT1(); }
        else            { CP_WAIT0(); }
        __syncthreads();

        const uint32_t sb = sbase + s * STAGE_B;
        const uint32_t Ah = sb, Al = sb + A_TILE_B;
        const uint32_t Bh = sb + 2 * A_TILE_B, Bl = sb + 2 * A_TILE_B + B_TILE_B;

        uint32_t ahi[2][2][4], alo[2][2][4], bhi[2][4][2], blo[2][4][2];
        #pragma unroll
        for (int ks = 0; ks < 2; ks++) {
            #pragma unroll
            for (int mt = 0; mt < 2; mt++) {
                int r = warpM * 32 + mt * 16 + (lane & 15);
                uint32_t off = r * PITCH_B + (ks * 2 + (lane >> 4)) * 16;
                ldsm4(ahi[ks][mt][0], ahi[ks][mt][1], ahi[ks][mt][2], ahi[ks][mt][3], Ah + off);
                ldsm4(alo[ks][mt][0], alo[ks][mt][1], alo[ks][mt][2], alo[ks][mt][3], Al + off);
            }
            #pragma unroll
            for (int tp = 0; tp < 2; tp++) {
                int nr = warpN * 32 + tp * 16 + ((lane >> 4) << 3) + (lane & 7);
                uint32_t off = nr * PITCH_B + (ks * 2 + ((lane >> 3) & 1)) * 16;
                ldsm4(bhi[ks][2 * tp][0], bhi[ks][2 * tp][1],
                      bhi[ks][2 * tp + 1][0], bhi[ks][2 * tp + 1][1], Bh + off);
                ldsm4(blo[ks][2 * tp][0], blo[ks][2 * tp][1],
                      blo[ks][2 * tp + 1][0], blo[ks][2 * tp + 1][1], Bl + off);
            }
        }
        #pragma unroll
        for (int ks = 0; ks < 2; ks++)
            #pragma unroll
            for (int mt = 0; mt < 2; mt++)
                #pragma unroll
                for (int nt = 0; nt < 4; nt++) {
                    mma16816(acc[mt][nt], ahi[ks][mt], bhi[ks][nt]);
                    mma16816(acc[mt][nt], ahi[ks][mt], blo[ks][nt]);
                    mma16816(acc[mt][nt], alo[ks][mt], bhi[ks][nt]);
                }
        __syncthreads();
    }

    #pragma unroll
    for (int mt = 0; mt < 2; mt++) {
        int r0 = m0 + warpM * 32 + mt * 16 + (lane >> 2);
        #pragma unroll
        for (int nt = 0; nt < 4; nt++) {
            int col = n0 + warpN * 32 + nt * 8 + (lane & 3) * 2;
            if (SPLITOUT) {
                bf16 h0, l0, h1, l1;
                split2(acc[mt][nt][0], h0, l0);
                split2(acc[mt][nt][1], h1, l1);
                *(bf162*)(Chi + (size_t)r0 * N + col) = bf162(h0, h1);
                *(bf162*)(Clo + (size_t)r0 * N + col) = bf162(l0, l1);
                split2(acc[mt][nt][2], h0, l0);
                split2(acc[mt][nt][3], h1, l1);
                *(bf162*)(Chi + (size_t)(r0 + 8) * N + col) = bf162(h0, h1);
                *(bf162*)(Clo + (size_t)(r0 + 8) * N + col) = bf162(l0, l1);
            } else {
                float2 v0 = {acc[mt][nt][0], acc[mt][nt][1]};
                float2 v1 = {acc[mt][nt][2], acc[mt][nt][3]};
                if (BIAS) {
                    float2 bv = *(const float2*)(bias + col);
                    v0.x += bv.x; v0.y += bv.y;
                    v1.x += bv.x; v1.y += bv.y;
                }
                *(float2*)(C + (size_t)r0 * N + col)       = v0;
                *(float2*)(C + (size_t)(r0 + 8) * N + col) = v1;
            }
        }
    }
}

// ======================= proj: elu1(slice @ projT) via HMMA =================
// grid (2 ftile, 128 rowtile, 32 z={h,sel}); CTA tile 128x128, K=64 one-shot.
// smem: Ah,Al,Bh,Bl each 128x144B = 73728 total.
static constexpr int PROJ_SMEM = 4 * 18432;

__global__ __launch_bounds__(256) void proj_mma()
{
    extern __shared__ char smem[];
    const uint32_t sbase = smem_u32(smem);
    const int tid = threadIdx.x;
    const int wid = tid >> 5, lane = tid & 31;
    const int warpM = wid & 3, warpN = wid >> 2;
    const int z = blockIdx.z;
    const int sel = z & 1, h = z >> 1;
    const int m0 = blockIdx.y * 128;
    const int fbase = blockIdx.x * 128;
    const int aoff = sel * 1024 + h * 64;

    // load A (qkv hi/lo slices) and B (projT hi/lo)
    #pragma unroll
    for (int i = 0; i < 16; i++) {
        int idx = tid + i * 256;
        int half = idx >> 11;            // 0: A, 1: B
        int idx2 = idx & 2047;
        int hl = idx2 >> 10;
        int rem = idx2 & 1023;
        int row = rem >> 3, ch = rem & 7;
        if (half == 0) {
            const bf16* g = (hl ? g_qkvl : g_qkvh) + (size_t)(m0 + row) * 3072 + aoff + ch * 8;
            cp16(sbase + hl * 18432 + row * PITCH_B + ch * 16, g);
        } else {
            const bf16* g = (hl ? g_projT_lo : g_projT_hi) + ((size_t)h * 256 + fbase + row) * 64 + ch * 8;
            cp16(sbase + 36864 + hl * 18432 + row * PITCH_B + ch * 16, g);
        }
    }
    CP_COMMIT();
    CP_WAIT0();
    __syncthreads();

    float acc[2][8][4];
    #pragma unroll
    for (int i = 0; i < 2; i++)
        #pragma unroll
        for (int j = 0; j < 8; j++)
            #pragma unroll
            for (int q = 0; q < 4; q++) acc[i][j][q] = 0.f;

    const uint32_t Ah = sbase, Al = sbase + 18432;
    const uint32_t Bh = sbase + 36864, Bl = sbase + 55296;

    #pragma unroll
    for (int ks = 0; ks < 4; ks++) {
        uint32_t ahi[2][4], alo[2][4];
        #pragma unroll
        for (int mt = 0; mt < 2; mt++) {
            int r = warpM * 32 + mt * 16 + (lane & 15);
            uint32_t off = r * PITCH_B + (ks * 2 + (lane >> 4)) * 16;
            ldsm4(ahi[mt][0], ahi[mt][1], ahi[mt][2], ahi[mt][3], Ah + off);
            ldsm4(alo[mt][0], alo[mt][1], alo[mt][2], alo[mt][3], Al + off);
        }
        #pragma unroll
        for (int tp = 0; tp < 4; tp++) {
            uint32_t bh[2][2], bl[2][2];
            int nr = warpN * 64 + tp * 16 + ((lane >> 4) << 3) + (lane & 7);
            uint32_t off = nr * PITCH_B + (ks * 2 + ((lane >> 3) & 1)) * 16;
            ldsm4(bh[0][0], bh[0][1], bh[1][0], bh[1][1], Bh + off);
            ldsm4(bl[0][0], bl[0][1], bl[1][0], bl[1][1], Bl + off);
            #pragma unroll
            for (int mt = 0; mt < 2; mt++)
                #pragma unroll
                for (int p = 0; p < 2; p++) {
                    mma16816(acc[mt][2 * tp + p], ahi[mt], bh[p]);
                    mma16816(acc[mt][2 * tp + p], ahi[mt], bl[p]);
                    mma16816(acc[mt][2 * tp + p], alo[mt], bh[p]);
                }
        }
    }

    bf16* oh = sel ? g_kph : g_qph;
    bf16* ol = sel ? g_kpl : g_qpl;
    const int b = m0 >> 12;
    const size_t bhbase = ((size_t)(b * 16 + h)) * 4096 * 256;

    float cs[16];
    #pragma unroll
    for (int i = 0; i < 16; i++) cs[i] = 0.f;

    #pragma unroll
    for (int mt = 0; mt < 2; mt++) {
        int rl0 = warpM * 32 + mt * 16 + (lane >> 2);
        #pragma unroll
        for (int nt = 0; nt < 8; nt++) {
            int col = warpN * 64 + nt * 8 + (lane & 3) * 2;
            float e[4];
            #pragma unroll
            for (int q = 0; q < 4; q++) {
                float v = acc[mt][nt][q];
                e[q] = v > 0.f ? v + 1.f : __expf(v);
                cs[nt * 2 + (q & 1)] += e[q];
            }
            int n0r = m0 + rl0 - b * 4096;   // row within (b, n)
            size_t o0 = bhbase + (size_t)n0r * 256 + fbase + col;
            size_t o1 = o0 + 8 * 256;
            bf16 h0, l0, h1, l1;
            split2(e[0], h0, l0); split2(e[1], h1, l1);
            *(bf162*)(oh + o0) = bf162(h0, h1);
            *(bf162*)(ol + o0) = bf162(l0, l1);
            split2(e[2], h0, l0); split2(e[3], h1, l1);
            *(bf162*)(oh + o1) = bf162(h0, h1);
            *(bf162*)(ol + o1) = bf162(l0, l1);
        }
    }

    if (sel == 1) {
        // deterministic per-CTA column sums -> g_kspart
        __syncthreads();
        float* sums = (float*)smem;     // [128 cols][32 slots]
        int slot = warpM * 8 + (lane >> 2);
        #pragma unroll
        for (int nt = 0; nt < 8; nt++)
            #pragma unroll
            for (int cp = 0; cp < 2; cp++) {
                int col = warpN * 64 + nt * 8 + (lane & 3) * 2 + cp;
                sums[col * 32 + slot] = cs[nt * 2 + cp];
            }
        __syncthreads();
        if (tid < 128) {
            float s = 0.f;
            #pragma unroll
            for (int i = 0; i < 32; i++) s += sums[tid * 32 + i];
            g_kspart[((size_t)blockIdx.y * 16 + h) * 256 + fbase + tid] = s;
        }
    }
}

// ======================= kv: v^T @ kproj via trans-HMMA =====================
// grid (4 ksplit, 64 bh). M=64(d), N=256(f), K=1024 chunk 32.
// A stored natural (k rows 32, 64 d cols) pitch 144; B (k rows 32, 256 f) pitch 528.
static constexpr int KV_A_T = 32 * 144;     // 4608
static constexpr int KV_B_T = 32 * 528;     // 16896
static constexpr int KV_STAGE = 2 * KV_A_T + 2 * KV_B_T;  // 43008
static constexpr int KV_SMEM = 2 * KV_STAGE;              // 86016

__global__ __launch_bounds__(256, 2) void kv_mma()
{
    extern __shared__ char smem[];
    const uint32_t sbase = smem_u32(smem);
    const int tid = threadIdx.x;
    const int wid = tid >> 5, lane = tid & 31;
    const int warpM = wid >> 2, warpN = wid & 3;   // 2M x 4N
    const int kc = blockIdx.x, bh = blockIdx.y;
    const int b = bh >> 4, h = bh & 15;

    float acc[2][8][4];
    #pragma unroll
    for (int i = 0; i < 2; i++)
        #pragma unroll
        for (int j = 0; j < 8; j++)
            #pragma unroll
            for (int q = 0; q < 4; q++) acc[i][j][q] = 0.f;

    auto load_stage = [&](int c, int s) {
        const uint32_t sb = sbase + s * KV_STAGE;
        const int n0 = kc * 1024 + c * 32;
        #pragma unroll
        for (int i = 0; i < 10; i++) {
            int idx = tid + i * 256;
            if (idx < 512) {
                int hl = idx >> 8, rem = idx & 255;
                int row = rem >> 3, ch = rem & 7;
                const bf16* g = (hl ? g_qkvl : g_qkvh) +
                    (size_t)(b * 4096 + n0 + row) * 3072 + 2048 + h * 64 + ch * 8;
                cp16(sb + hl * KV_A_T + row * 144 + ch * 16, g);
            } else {
                int idx2 = idx - 512;
                int hl = idx2 >> 10, rem = idx2 & 1023;
                int row = rem >> 5, ch = rem & 31;
                const bf16* g = (hl ? g_kpl : g_kph) +
                    ((size_t)bh * 4096 + n0 + row) * 256 + ch * 8;
                cp16(sb + 2 * KV_A_T + hl * KV_B_T + row * 528 + ch * 16, g);
            }
        }
        CP_COMMIT();
    };

    load_stage(0, 0);
    for (int c = 0; c < 32; c++) {
        const int s = c & 1;
        if (c + 1 < 32) { load_stage(c + 1, s ^ 1); CP_WAIT1(); }
        else            { CP_WAIT0(); }
        __syncthreads();

        const uint32_t sb = sbase + s * KV_STAGE;
        const uint32_t Ah = sb, Al = sb + KV_A_T;
        const uint32_t Bh = sb + 2 * KV_A_T, Bl = sb + 2 * KV_A_T + KV_B_T;

        #pragma unroll
        for (int ks = 0; ks < 2; ks++) {
            const int kbase = ks * 16;
            uint32_t ahi[2][4], alo[2][4];
            #pragma unroll
            for (int mt = 0; mt < 2; mt++) {
                int md = warpM * 32 + mt * 16 + ((lane >> 3) & 1) * 8;
                int krow = kbase + (lane >> 4) * 8 + (lane & 7);
                uint32_t off = krow * 144 + md * 2;
                ldsm4t(ahi[mt][0], ahi[mt][1], ahi[mt][2], ahi[mt][3], Ah + off);
                ldsm4t(alo[mt][0], alo[mt][1], alo[mt][2], alo[mt][3], Al + off);
            }
            #pragma unroll
            for (int tp = 0; tp < 4; tp++) {
                uint32_t bh2[2][2], bl2[2][2];
                int krow = kbase + ((lane >> 3) & 1) * 8 + (lane & 7);
                int ncol = warpN * 64 + tp * 16 + (lane >> 4) * 8;
                uint32_t off = krow * 528 + ncol * 2;
                ldsm4t(bh2[0][0], bh2[0][1], bh2[1][0], bh2[1][1], Bh + off);
                ldsm4t(bl2[0][0], bl2[0][1], bl2[1][0], bl2[1][1], Bl + off);
                #pragma unroll
                for (int mt = 0; mt < 2; mt++)
                    #pragma unroll
                    for (int p = 0; p < 2; p++) {
                        mma16816(acc[mt][2 * tp + p], ahi[mt], bh2[p]);
                        mma16816(acc[mt][2 * tp + p], ahi[mt], bl2[p]);
                        mma16816(acc[mt][2 * tp + p], alo[mt], bh2[p]);
                    }
            }
        }
        __syncthreads();
    }

    float* out = g_kvpart + ((size_t)kc * 64 + bh) * 16384;
    #pragma unroll
    for (int mt = 0; mt < 2; mt++) {
        int d0 = warpM * 32 + mt * 16 + (lane >> 2);
        #pragma unroll
        for (int nt = 0; nt < 8; nt++) {
            int col = warpN * 64 + nt * 8 + (lane & 3) * 2;
            *(float2*)(out + (size_t)d0 * 256 + col) =
                make_float2(acc[mt][nt][0], acc[mt][nt][1]);
            *(float2*)(out + (size_t)(d0 + 8) * 256 + col) =
                make_float2(acc[mt][nt][2], acc[mt][nt][3]);
        }
    }
}

// ======================= kv combine: partials -> kvT hi/lo + ksum row =======
__global__ void kv_combine()
{
    const int row = blockIdx.x;       // 0..79
    const int bh = blockIdx.y;
    const int f = threadIdx.x;        // 0..255
    float s = 0.f;
    if (row < 64) {
        #pragma unroll
        for (int kc = 0; kc < 4; kc++)
            s += g_kvpart[((size_t)kc * 64 + bh) * 16384 + row * 256 + f];
    } else if (row == 64) {
        const int b = bh >> 4, h = bh & 15;
        for (int i = 0; i < 32; i++)
            s += g_kspart[((size_t)(b * 32 + i) * 16 + h) * 256 + f];
    }
    bf16 hh, ll;
    split2(s, hh, ll);
    g_kvTh[((size_t)bh * 80 + row) * 256 + f] = hh;
    g_kvTl[((size_t)bh * 80 + row) * 256 + f] = ll;
}

// ======================= attn: qproj @ [kv|ksum] + z-norm via HMMA ==========
// grid (32 ntile, 64 bh). CTA 128 x 80, K=256 chunk 32.
// A (128 rows, k32) pitch 80; B (80 rows, k32) pitch 80.
static constexpr int AT_A_T = 128 * 80;    // 10240
static constexpr int AT_B_T = 80 * 80;     // 6400
static constexpr int AT_STAGE = 2 * AT_A_T + 2 * AT_B_T;  // 33280
static constexpr int AT_SMEM = 2 * AT_STAGE;              // 66560

__global__ __launch_bounds__(256) void attn_mma()
{
    extern __shared__ char smem[];
    __shared__ float zs[128];
    const uint32_t sbase = smem_u32(smem);
    const int tid = threadIdx.x;
    const int wid = tid >> 5, lane = tid & 31;
    const int warpM = wid & 3, warpN = wid >> 2;   // 4M x 2N
    const int nbase = blockIdx.x * 128;
    const int bh = blockIdx.y;
    const int b = bh >> 4, h = bh & 15;

    float acc[2][5][4];
    #pragma unroll
    for (int i = 0; i < 2; i++)
        #pragma unroll
        for (int j = 0; j < 5; j++)
            #pragma unroll
            for (int q = 0; q < 4; q++) acc[i][j][q] = 0.f;

    auto load_stage = [&](int c, int s) {
        const uint32_t sb = sbase + s * AT_STAGE;
        const int k0 = c * 32;
        #pragma unroll
        for (int i = 0; i < 7; i++) {
            int idx = tid + i * 256;
            if (idx >= 1664) break;
            if (idx < 1024) {
                int hl = idx >> 9, rem = idx & 511;
                int row = rem >> 2, ch = rem & 3;
                const bf16* g = (hl ? g_qpl : g_qph) +
                    ((size_t)bh * 4096 + nbase + row) * 256 + k0 + ch * 8;
                cp16(sb + hl * AT_A_T + row * 80 + ch * 16, g);
            } else {
                int idx2 = idx - 1024;
                int hl = idx2 >= 320 ? 1 : 0;
                int rem = idx2 - hl * 320;
                int row = rem >> 2, ch = rem & 3;
                const bf16* g = (hl ? g_kvTl : g_kvTh) +
                    ((size_t)bh * 80 + row) * 256 + k0 + ch * 8;
                cp16(sb + 2 * AT_A_T + hl * AT_B_T + row * 80 + ch * 16, g);
            }
        }
        CP_COMMIT();
    };

    load_stage(0, 0);
    for (int c = 0; c < 8; c++) {
        const int s = c & 1;
        if (c + 1 < 8) { load_stage(c + 1, s ^ 1); CP_WAIT1(); }
        else           { CP_WAIT0(); }
        __syncthreads();

        const uint32_t sb = sbase + s * AT_STAGE;
        const uint32_t Ah = sb, Al = sb + AT_A_T;
        const uint32_t Bh = sb + 2 * AT_A_T, Bl = sb + 2 * AT_A_T + AT_B_T;

        #pragma unroll
        for (int ks = 0; ks < 2; ks++) {
            uint32_t ahi[2][4], alo[2][4];
            #pragma unroll
            for (int mt = 0; mt < 2; mt++) {
                int r = warpM * 32 + mt * 16 + (lane & 15);
                uint32_t off = r * 80 + (ks * 2 + (lane >> 4)) * 16;
                ldsm4(ahi[mt][0], ahi[mt][1], ahi[mt][2], ahi[mt][3], Ah + off);
                ldsm4(alo[mt][0], alo[mt][1], alo[mt][2], alo[mt][3], Al + off);
            }
            #pragma unroll
            for (int tp = 0; tp < 2; tp++) {
                uint32_t bh2[2][2], bl2[2][2];
                int nr = warpN * 40 + tp * 16 + ((lane >> 4) << 3) + (lane & 7);
                uint32_t off = nr * 80 + (ks * 2 + ((lane >> 3) & 1)) * 16;
                ldsm4(bh2[0][0], bh2[0][1], bh2[1][0], bh2[1][1], Bh + off);
                ldsm4(bl2[0][0], bl2[0][1], bl2[1][0], bl2[1][1], Bl + off);
                #pragma unroll
                for (int mt = 0; mt < 2; mt++)
                    #pragma unroll
                    for (int p = 0; p < 2; p++) {
                        mma16816(acc[mt][2 * tp + p], ahi[mt], bh2[p]);
                        mma16816(acc[mt][2 * tp + p], ahi[mt], bl2[p]);
                        mma16816(acc[mt][2 * tp + p], alo[mt], bh2[p]);
                    }
            }
            {   // nt = 4 (cols 32..39 of warp)
                uint32_t bh2[2], bl2[2];
                int nr = warpN * 40 + 32 + (lane & 7);
                uint32_t off = nr * 80 + (ks * 2 + ((lane >> 3) & 1)) * 16;
                ldsm2(bh2[0], bh2[1], Bh + off);
                ldsm2(bl2[0], bl2[1], Bl + off);
                #pragma unroll
                for (int mt = 0; mt < 2; mt++) {
                    mma16816(acc[mt][4], ahi[mt], bh2);
                    mma16816(acc[mt][4], ahi[mt], bl2);
                    mma16816(acc[mt][4], alo[mt], bh2);
                }
            }
        }
        __syncthreads();
    }

    // publish z column (col 64 = warpN 1, tp-tile col offset 24 -> nt 3)
    if (warpN == 1 && (lane & 3) == 0) {
        #pragma unroll
        for (int mt = 0; mt < 2; mt++) {
            int r0 = warpM * 32 + mt * 16 + (lane >> 2);
            zs[r0] = acc[mt][3][0];
            zs[r0 + 8] = acc[mt][3][2];
        }
    }
    __syncthreads();

    #pragma unroll
    for (int mt = 0; mt < 2; mt++) {
        int rl0 = warpM * 32 + mt * 16 + (lane >> 2);
        float zi0 = 1.0f / (zs[rl0] + 1e-8f);
        float zi1 = 1.0f / (zs[rl0 + 8] + 1e-8f);
        #pragma unroll
        for (int nt = 0; nt < 5; nt++) {
            int col = warpN * 40 + nt * 8 + (lane & 3) * 2;
            if (col >= 64) continue;
            size_t o0 = ((size_t)(b * 4096 + nbase + rl0)) * 1024 + h * 64 + col;
            size_t o1 = o0 + 8 * 1024;
            bf16 h0, l0, h1, l1;
            split2(acc[mt][nt][0] * zi0, h0, l0);
            split2(acc[mt][nt][1] * zi0, h1, l1);
            *(bf162*)(g_attn_hi + o0) = bf162(h0, h1);
            *(bf162*)(g_attn_lo + o0) = bf162(l0, l1);
            split2(acc[mt][nt][2] * zi1, h0, l0);
            split2(acc[mt][nt][3] * zi1, h1, l1);
            *(bf162*)(g_attn_hi + o1) = bf162(h0, h1);
            *(bf162*)(g_attn_lo + o1) = bf162(l0, l1);
        }
    }
}

// ======================= conversion kernels =================================
__global__ void split_f32(const float* __restrict__ in,
                          bf16* __restrict__ hi, bf16* __restrict__ lo, int n4)
{
    int i = blockIdx.x * blockDim.x + threadIdx.x;
    if (i >= n4) return;
    float4 v = ((const float4*)in)[i];
    bf16 h0, l0, h1, l1, h2, l2, h3, l3;
    split2(v.x, h0, l0); split2(v.y, h1, l1);
    split2(v.z, h2, l2); split2(v.w, h3, l3);
    ((bf162*)hi)[2 * i]     = bf162(h0, h1);
    ((bf162*)hi)[2 * i + 1] = bf162(h2, h3);
    ((bf162*)lo)[2 * i]     = bf162(l0, l1);
    ((bf162*)lo)[2 * i + 1] = bf162(l2, l3);
}

__global__ void split_wT(const float* __restrict__ w,
                         bf16* __restrict__ thi, bf16* __restrict__ tlo,
                         int K, int N)
{
    __shared__ float t[32][33];
    int bx = blockIdx.x * 32, by = blockIdx.y * 32;
    int tx = threadIdx.x, ty = threadIdx.y;
    #pragma unroll
    for (int i = 0; i < 32; i += 8)
        t[ty + i][tx] = w[(size_t)(by + ty + i) * N + bx + tx];
    __syncthreads();
    #pragma unroll
    for (int i = 0; i < 32; i += 8) {
        bf16 hh, ll;
        split2(t[tx][ty + i], hh, ll);
        size_t o = (size_t)(bx + ty + i) * K + by + tx;
        thi[o] = hh;
        tlo[o] = ll;
    }
}

// proj (16, 64, 256) fp32 -> projT (16, 256, 64) bf16 hi/lo
__global__ void split_projT(const float* __restrict__ proj)
{
    __shared__ float t[64][33];
    const int f0 = blockIdx.x * 32;
    const int h = blockIdx.y;
    const int tid = threadIdx.x;
    #pragma unroll
    for (int i = 0; i < 8; i++) {
        int e = tid + i * 256;
        int d = e >> 5, fi = e & 31;
        t[d][fi] = proj[(size_t)h * 16384 + d * 256 + f0 + fi];
    }
    __syncthreads();
    #pragma unroll
    for (int i = 0; i < 8; i++) {
        int e = tid + i * 256;
        int fi = e >> 6, d = e & 63;
        bf16 hh, ll;
        split2(t[d][fi], hh, ll);
        size_t o = ((size_t)h * 256 + f0 + fi) * 64 + d;
        g_projT_hi[o] = hh;
        g_projT_lo[o] = ll;
    }
}

// ===========================================================================
extern "C" void kernel_launch(void* const* d_in, const int* in_sizes, int n_in,
                              void* d_out, int out_size)
{
    const float* x      = (const float*)d_in[0];
    const float* w_qkv  = (const float*)d_in[1];
    const float* proj   = (const float*)d_in[2];
    const float* w_out  = (const float*)d_in[3];
    const float* b_out  = (const float*)d_in[4];
    float* out = (float*)d_out;

    cudaFuncSetAttribute(hmma_gemm<false, true>,
                         cudaFuncAttributeMaxDynamicSharedMemorySize, GEMM_SMEM);
    cudaFuncSetAttribute(hmma_gemm<true, false>,
                         cudaFuncAttributeMaxDynamicSharedMemorySize, GEMM_SMEM);
    cudaFuncSetAttribute(proj_mma,
                         cudaFuncAttributeMaxDynamicSharedMemorySize, PROJ_SMEM);
    cudaFuncSetAttribute(kv_mma,
                         cudaFuncAttributeMaxDynamicSharedMemorySize, KV_SMEM);
    cudaFuncSetAttribute(attn_mma,
                         cudaFuncAttributeMaxDynamicSharedMemorySize, AT_SMEM);

    bf16 *xhi, *xlo, *wqh, *wql, *woh, *wol, *qh, *ql, *ahi, *alo;
    cudaGetSymbolAddress((void**)&xhi, g_xhi);
    cudaGetSymbolAddress((void**)&xlo, g_xlo);
    cudaGetSymbolAddress((void**)&wqh, g_wqkvT_hi);
    cudaGetSymbolAddress((void**)&wql, g_wqkvT_lo);
    cudaGetSymbolAddress((void**)&woh, g_woutT_hi);
    cudaGetSymbolAddress((void**)&wol, g_woutT_lo);
    cudaGetSymbolAddress((void**)&qh, g_qkvh);
    cudaGetSymbolAddress((void**)&ql, g_qkvl);
    cudaGetSymbolAddress((void**)&ahi, g_attn_hi);
    cudaGetSymbolAddress((void**)&alo, g_attn_lo);

    // conversions
    split_f32<<<16384, 256>>>(x, xhi, xlo, 16777216 / 4);
    split_wT<<<dim3(96, 32), dim3(32, 8)>>>(w_qkv, wqh, wql, 1024, 3072);
    split_wT<<<dim3(32, 32), dim3(32, 8)>>>(w_out, woh, wol, 1024, 1024);
    split_projT<<<dim3(8, 16), 256>>>(proj);

    // qkv = x @ w_qkv -> hi/lo bf16
    hmma_gemm<false, true><<<dim3(48, 128), 256, GEMM_SMEM>>>(
        xhi, xlo, wqh, wql, nullptr, nullptr, qh, ql, 3072, 1024);

    // feature projection + elu1 (+ksum partials)
    proj_mma<<<dim3(2, 128, 32), 256, PROJ_SMEM>>>();

    // kv state (trans-HMMA, k-split) + combine with ksum
    kv_mma<<<dim3(4, 64), 256, KV_SMEM>>>();
    kv_combine<<<dim3(80, 64), 256>>>();

    // attn + z-normalization -> attn hi/lo
    attn_mma<<<dim3(32, 64), 256, AT_SMEM>>>();

    // out = attn @ w_out + b_out
    hmma_gemm<true, false><<<dim3(16, 128), 256, GEMM_SMEM>>>(
        ahi, alo, woh, wol, b_out, out, nullptr, nullptr, 1024, 1024);
}